// round 1
// baseline (speedup 1.0000x reference)
#include <cuda_runtime.h>
#include <cstdint>

// Problem constants
#define BATCH    16
#define ZDIM     512
#define TSEQ     4096
#define NGROUPS  2
#define NENTRIES 320
#define VDIM     128
#define MROWS    (BATCH * TSEQ)          // 65536
#define NCOLS    (NGROUPS * NENTRIES)    // 640
#define KDIM     ZDIM                    // 512
#define LOGITS_ELEMS ((size_t)MROWS * NCOLS)   // 41,943,040

// GEMM tiling
#define BM 128
#define BN 64
#define BK 16
#define TM 8
#define TN 4
// 256 threads = 16x16 thread grid

__global__ __launch_bounds__(256)
void pq_gemm_kernel(const float* __restrict__ x,      // (B, Z, T)
                    const float* __restrict__ w,      // (640, 512)
                    const float* __restrict__ bias,   // (640,)
                    float* __restrict__ out)          // (M, 640) logits
{
    __shared__ float As[BK][BM];        // k-major, m contiguous (512B rows, f4-aligned)
    __shared__ float Bs[BK][BN + 4];    // pad 4 floats -> row stride 272B (16B aligned)

    const int tid = threadIdx.x;
    const int tx  = tid & 15;            // 0..15  (N direction)
    const int ty  = tid >> 4;            // 0..15  (M direction)

    const int m0 = blockIdx.x * BM;      // tile never crosses batch boundary (128 | 4096)
    const int n0 = blockIdx.y * BN;
    const int b  = m0 >> 12;             // m0 / 4096
    const int t0 = m0 & 4095;

    const float* xbase = x + (size_t)b * ZDIM * TSEQ + t0;   // + k*TSEQ + m_local

    float acc[TM][TN];
#pragma unroll
    for (int i = 0; i < TM; i++)
#pragma unroll
        for (int j = 0; j < TN; j++) acc[i][j] = 0.0f;

    // A-tile load mapping: 2 passes of 256 float4 covering 16x128 floats
    // B-tile load mapping: 1 pass of 256 float4 covering 64x16 floats
    const int a_c4 = tid & 31;           // float4 column within 128-wide m row
    const int b_n  = tid >> 2;           // 0..63
    const int b_kq = tid & 3;            // which float4 of the 16-float k chunk

    for (int kk = 0; kk < KDIM; kk += BK) {
        // ---- load A tile (coalesced float4, m-contiguous) ----
        {
            int kr0 = tid >> 5;                       // 0..7
            float4 va0 = *(const float4*)(xbase + (size_t)(kk + kr0) * TSEQ + a_c4 * 4);
            float4 va1 = *(const float4*)(xbase + (size_t)(kk + kr0 + 8) * TSEQ + a_c4 * 4);
            ((float4*)As[kr0])[a_c4]     = va0;
            ((float4*)As[kr0 + 8])[a_c4] = va1;
        }
        // ---- load B tile (float4 along k, transposed scalar store) ----
        {
            float4 vb = *(const float4*)(w + (size_t)(n0 + b_n) * KDIM + kk + b_kq * 4);
            Bs[b_kq * 4 + 0][b_n] = vb.x;
            Bs[b_kq * 4 + 1][b_n] = vb.y;
            Bs[b_kq * 4 + 2][b_n] = vb.z;
            Bs[b_kq * 4 + 3][b_n] = vb.w;
        }
        __syncthreads();

#pragma unroll
        for (int k = 0; k < BK; k++) {
            float4 a0 = ((const float4*)As[k])[ty * 2];
            float4 a1 = ((const float4*)As[k])[ty * 2 + 1];
            float4 bv = ((const float4*)Bs[k])[tx];
            float af[TM] = {a0.x, a0.y, a0.z, a0.w, a1.x, a1.y, a1.z, a1.w};
            float bf[TN] = {bv.x, bv.y, bv.z, bv.w};
#pragma unroll
            for (int i = 0; i < TM; i++)
#pragma unroll
                for (int j = 0; j < TN; j++)
                    acc[i][j] = fmaf(af[i], bf[j], acc[i][j]);
        }
        __syncthreads();
    }

    // ---- epilogue: add bias, store float4 rows ----
    float4 bb = *(const float4*)(bias + n0 + tx * 4);
#pragma unroll
    for (int i = 0; i < TM; i++) {
        int m_row = m0 + ty * TM + i;
        float4 v = make_float4(acc[i][0] + bb.x, acc[i][1] + bb.y,
                               acc[i][2] + bb.z, acc[i][3] + bb.w);
        *(float4*)(out + (size_t)m_row * NCOLS + n0 + tx * 4) = v;
    }
}

// One warp per (b, t, g) group: argmax over 320 entries of logits+gumbel,
// then copy the selected 128-float codevector row to q.
__global__ __launch_bounds__(256)
void pq_argmax_gather_kernel(const float* __restrict__ logits,   // (BT, 640)
                             const float* __restrict__ gumbel,   // (BT, 2, 320)
                             const float* __restrict__ cv,       // (640, 128)
                             float* __restrict__ q)              // (BT, 256)
{
    const int warp = (blockIdx.x * blockDim.x + threadIdx.x) >> 5;
    const int lane = threadIdx.x & 31;
    const int total = MROWS * NGROUPS;           // 131072
    if (warp >= total) return;

    const int bt = warp >> 1;
    const int g  = warp & 1;

    const float* lp = logits + (size_t)bt * NCOLS + g * NENTRIES;
    const float* gp = gumbel + (size_t)bt * NCOLS + g * NENTRIES;

    float best = -3.4e38f;
    int   bidx = 0;
#pragma unroll
    for (int j = 0; j < NENTRIES / 32; j++) {
        int e = lane + j * 32;
        float v = lp[e] + gp[e];
        if (v > best) { best = v; bidx = e; }     // ascending e -> keeps lowest idx on tie
    }
    // warp argmax reduction, lowest-index tiebreak
#pragma unroll
    for (int off = 16; off > 0; off >>= 1) {
        float ov = __shfl_down_sync(0xffffffffu, best, off);
        int   oi = __shfl_down_sync(0xffffffffu, bidx, off);
        if (ov > best || (ov == best && oi < bidx)) { best = ov; bidx = oi; }
    }
    bidx = __shfl_sync(0xffffffffu, bidx, 0);

    const float4* src = (const float4*)(cv + ((size_t)g * NENTRIES + bidx) * VDIM);
    float4*       dst = (float4*)(q + (size_t)bt * (NGROUPS * VDIM) + g * VDIM);
    dst[lane] = src[lane];
}

extern "C" void kernel_launch(void* const* d_in, const int* in_sizes, int n_in,
                              void* d_out, int out_size) {
    const float* x      = (const float*)d_in[0];   // (16, 512, 4096)
    const float* gumbel = (const float*)d_in[1];   // (16, 4096, 2, 320)
    const float* proj_w = (const float*)d_in[2];   // (640, 512)
    const float* proj_b = (const float*)d_in[3];   // (640,)
    const float* cv     = (const float*)d_in[4];   // (1, 640, 128)

    float* out    = (float*)d_out;
    float* logits = out;                           // first output, 41,943,040 floats
    float* q      = out + LOGITS_ELEMS;            // second output, 16,777,216 floats

    dim3 grid(MROWS / BM, NCOLS / BN);             // (512, 10)
    pq_gemm_kernel<<<grid, 256>>>(x, proj_w, proj_b, logits);

    int warps = MROWS * NGROUPS;                   // 131072
    int threads = 256;
    int blocks = (warps * 32 + threads - 1) / threads;  // 16384
    pq_argmax_gather_kernel<<<blocks, threads>>>(logits, gumbel, cv, q);
}

// round 3
// speedup vs baseline: 1.7890x; 1.7890x over previous
#include <cuda_runtime.h>
#include <cuda_bf16.h>
#include <cstdint>

// ---------------- problem constants ----------------
#define BATCH    16
#define ZDIM     512
#define TSEQ     4096
#define NGROUPS  2
#define NENTRIES 320
#define VDIM     128
#define MROWS    (BATCH * TSEQ)          // 65536
#define NCOLS    (NGROUPS * NENTRIES)    // 640
#define KDIM     ZDIM                    // 512
#define LOGITS_ELEMS ((size_t)MROWS * NCOLS)

// ---------------- GEMM tiling ----------------
#define M_TILE   128
#define N_TILE   128
#define KC       32                      // k per chunk (bf16 elements)
#define NSEG     3
#define CHUNKS_PER_SEG (KDIM / KC)       // 16
#define NCHUNKS  (NSEG * CHUNKS_PER_SEG) // 48
#define STAGES   4
#define STAGE_BYTES 16384                // A 8KB + B 8KB
#define SMEM_BYTES (STAGES * STAGE_BYTES)  // 64 KB
#define THREADS  256

// ---------------- device scratch (bf16 splits) ----------------
__device__ __nv_bfloat16 g_xhi[(size_t)MROWS * KDIM];
__device__ __nv_bfloat16 g_xlo[(size_t)MROWS * KDIM];
__device__ __nv_bfloat16 g_whi[NCOLS * KDIM];
__device__ __nv_bfloat16 g_wlo[NCOLS * KDIM];

__device__ __forceinline__ uint32_t smem_u32(const void* p) {
    uint32_t a;
    asm("{ .reg .u64 t; cvta.to.shared.u64 t, %1; cvt.u32.u64 %0, t; }" : "=r"(a) : "l"(p));
    return a;
}

#define CP_ASYNC16(dst, src) \
    asm volatile("cp.async.cg.shared.global [%0], [%1], 16;" :: "r"(dst), "l"(src))
#define CP_COMMIT() asm volatile("cp.async.commit_group;")
#define CP_WAIT2()  asm volatile("cp.async.wait_group 2;")

__device__ __forceinline__ void ldm_x4(uint32_t addr, uint32_t& r0, uint32_t& r1,
                                       uint32_t& r2, uint32_t& r3) {
    asm volatile("ldmatrix.sync.aligned.m8n8.x4.shared.b16 {%0,%1,%2,%3}, [%4];"
                 : "=r"(r0), "=r"(r1), "=r"(r2), "=r"(r3) : "r"(addr));
}

__device__ __forceinline__ void mma_bf16(float& c0, float& c1, float& c2, float& c3,
                                         uint32_t a0, uint32_t a1, uint32_t a2, uint32_t a3,
                                         uint32_t b0, uint32_t b1) {
    asm volatile("mma.sync.aligned.m16n8k16.row.col.f32.bf16.bf16.f32 "
                 "{%0,%1,%2,%3}, {%4,%5,%6,%7}, {%8,%9}, {%0,%1,%2,%3};"
                 : "+f"(c0), "+f"(c1), "+f"(c2), "+f"(c3)
                 : "r"(a0), "r"(a1), "r"(a2), "r"(a3), "r"(b0), "r"(b1));
}

// smem slot swizzle: 16B unit column within a 64B row, XORed so ldmatrix is
// conflict-free: slot' = c16 ^ ((row >> 1) & 3)
__device__ __forceinline__ uint32_t sw_off(int row, int c16) {
    return (uint32_t)(row * 64 + ((c16 ^ ((row >> 1) & 3)) << 4));
}

// ============================================================
// Pre-pass 1: split proj_w (640, 512) fp32 -> bf16 hi/lo
// ============================================================
__global__ __launch_bounds__(1024)
void split_w_kernel(const float* __restrict__ w) {
    int idx = blockIdx.x * blockDim.x + threadIdx.x;
    if (idx < NCOLS * KDIM) {
        float v = w[idx];
        __nv_bfloat16 hi = __float2bfloat16(v);
        g_whi[idx] = hi;
        g_wlo[idx] = __float2bfloat16(v - __bfloat162float(hi));
    }
}

// ============================================================
// Pre-pass 2: transpose x (B, Z, T) -> (B*T, Z), split hi/lo bf16
// ============================================================
__global__ __launch_bounds__(256)
void split_x_kernel(const float* __restrict__ x) {
    __shared__ float tile[32][33];
    const int b  = blockIdx.z;
    const int k0 = blockIdx.y * 32;
    const int t0 = blockIdx.x * 32;
    const int tx = threadIdx.x;
    const int ty = threadIdx.y;
#pragma unroll
    for (int i = 0; i < 4; i++) {
        int kr = ty + i * 8;
        tile[kr][tx] = x[((size_t)b * KDIM + (k0 + kr)) * TSEQ + t0 + tx];
    }
    __syncthreads();
#pragma unroll
    for (int i = 0; i < 4; i++) {
        int tr = ty + i * 8;
        float v = tile[tx][tr];
        __nv_bfloat16 hi = __float2bfloat16(v);
        size_t o = ((size_t)b * TSEQ + t0 + tr) * KDIM + k0 + tx;
        g_xhi[o] = hi;
        g_xlo[o] = __float2bfloat16(v - __bfloat162float(hi));
    }
}

// ============================================================
// GEMM: logits = [xhi|xlo] x [whi|wlo]^T (3-product split) + bias
// mma.sync bf16, cp.async 4-stage pipeline.
// grid = (NCOLS/N_TILE, MROWS/M_TILE) = (5, 512), 256 threads.
// ============================================================
__global__ __launch_bounds__(THREADS, 2)
void pq_gemm_kernel(const float* __restrict__ bias,
                    float* __restrict__ logits)
{
    extern __shared__ char smem[];
    const uint32_t sbase = smem_u32(smem);
    const int tid  = threadIdx.x;
    const int wid  = tid >> 5;
    const int lane = tid & 31;
    const int m0   = blockIdx.y * M_TILE;
    const int n0   = blockIdx.x * N_TILE;

    const int mwarp = wid >> 1;          // 0..3
    const int nwarp = wid & 1;           // 0..1

    float acc[2][8][4];
#pragma unroll
    for (int mi = 0; mi < 2; mi++)
#pragma unroll
        for (int nf = 0; nf < 8; nf++)
#pragma unroll
            for (int r = 0; r < 4; r++) acc[mi][nf][r] = 0.0f;

    // per-thread load mapping: row = tid>>1 (0..127), c16 base = (tid&1)*2
    const int lrow = tid >> 1;
    const int lcb  = (tid & 1) * 2;

    auto issue_chunk = [&](int c) {
        const int seg = c >> 4;
        const int kk  = (c & 15) * KC;
        const __nv_bfloat16* Ag = (seg == 2) ? g_xlo : g_xhi;
        const __nv_bfloat16* Bg = (seg == 1) ? g_wlo : g_whi;
        const uint32_t st = sbase + (uint32_t)(c & (STAGES - 1)) * STAGE_BYTES;
#pragma unroll
        for (int u = 0; u < 2; u++) {
            int c16 = lcb + u;
            uint32_t so = sw_off(lrow, c16);
            const __nv_bfloat16* ga = Ag + (size_t)(m0 + lrow) * KDIM + kk + c16 * 8;
            CP_ASYNC16(st + so, ga);
            const __nv_bfloat16* gb = Bg + (size_t)(n0 + lrow) * KDIM + kk + c16 * 8;
            CP_ASYNC16(st + 8192 + so, gb);
        }
        CP_COMMIT();
    };

    // prologue: fill 3 stages
    issue_chunk(0);
    issue_chunk(1);
    issue_chunk(2);

    for (int c = 0; c < NCHUNKS; ++c) {
        CP_WAIT2();                       // chunk c resident
        __syncthreads();                  // visible to all warps; stage (c-1)&3 free
        if (c + STAGES - 1 < NCHUNKS) issue_chunk(c + STAGES - 1);
        else CP_COMMIT();                 // keep group count aligned

        const uint32_t st = sbase + (uint32_t)(c & (STAGES - 1)) * STAGE_BYTES;
#pragma unroll
        for (int ks = 0; ks < 2; ks++) {
            uint32_t a[2][4];
#pragma unroll
            for (int mi = 0; mi < 2; mi++) {
                int row = mwarp * 32 + mi * 16 + (lane & 15);
                int c16 = ks * 2 + (lane >> 4);
                ldm_x4(st + sw_off(row, c16), a[mi][0], a[mi][1], a[mi][2], a[mi][3]);
            }
            uint32_t b[4][4];
#pragma unroll
            for (int j = 0; j < 4; j++) {
                int row = nwarp * 64 + j * 16 + (lane & 7) + ((lane >> 4) << 3);
                int c16 = ks * 2 + ((lane >> 3) & 1);
                ldm_x4(st + 8192 + sw_off(row, c16), b[j][0], b[j][1], b[j][2], b[j][3]);
            }
#pragma unroll
            for (int mi = 0; mi < 2; mi++)
#pragma unroll
                for (int nf = 0; nf < 8; nf++) {
                    int j = nf >> 1;
                    int h = (nf & 1) * 2;
                    mma_bf16(acc[mi][nf][0], acc[mi][nf][1], acc[mi][nf][2], acc[mi][nf][3],
                             a[mi][0], a[mi][1], a[mi][2], a[mi][3],
                             b[j][h], b[j][h + 1]);
                }
        }
    }

    // ---- epilogue: bias add + store ----
#pragma unroll
    for (int nf = 0; nf < 8; nf++) {
        int col = n0 + nwarp * 64 + nf * 8 + (lane & 3) * 2;
        float b0 = __ldg(bias + col);
        float b1 = __ldg(bias + col + 1);
#pragma unroll
        for (int mi = 0; mi < 2; mi++) {
            int row = m0 + mwarp * 32 + mi * 16 + (lane >> 2);
            float2 v0 = make_float2(acc[mi][nf][0] + b0, acc[mi][nf][1] + b1);
            float2 v1 = make_float2(acc[mi][nf][2] + b0, acc[mi][nf][3] + b1);
            *(float2*)(logits + (size_t)row * NCOLS + col)       = v0;
            *(float2*)(logits + (size_t)(row + 8) * NCOLS + col) = v1;
        }
    }
}

// ============================================================
// Argmax + gather (round-1 kernel; measured at DRAM roofline)
// ============================================================
__global__ __launch_bounds__(256)
void pq_argmax_gather_kernel(const float* __restrict__ logits,
                             const float* __restrict__ gumbel,
                             const float* __restrict__ cv,
                             float* __restrict__ q)
{
    const int warp = (blockIdx.x * blockDim.x + threadIdx.x) >> 5;
    const int lane = threadIdx.x & 31;
    if (warp >= MROWS * NGROUPS) return;

    const int bt = warp >> 1;
    const int g  = warp & 1;

    const float* lp = logits + (size_t)bt * NCOLS + g * NENTRIES;
    const float* gp = gumbel + (size_t)bt * NCOLS + g * NENTRIES;

    float best = -3.4e38f;
    int   bidx = 0;
#pragma unroll
    for (int j = 0; j < NENTRIES / 32; j++) {
        int e = lane + j * 32;
        float v = lp[e] + gp[e];
        if (v > best) { best = v; bidx = e; }
    }
#pragma unroll
    for (int off = 16; off > 0; off >>= 1) {
        float ov = __shfl_down_sync(0xffffffffu, best, off);
        int   oi = __shfl_down_sync(0xffffffffu, bidx, off);
        if (ov > best || (ov == best && oi < bidx)) { best = ov; bidx = oi; }
    }
    bidx = __shfl_sync(0xffffffffu, bidx, 0);

    const float4* src = (const float4*)(cv + ((size_t)g * NENTRIES + bidx) * VDIM);
    float4*       dst = (float4*)(q + (size_t)bt * (NGROUPS * VDIM) + g * VDIM);
    dst[lane] = src[lane];
}

// ============================================================
extern "C" void kernel_launch(void* const* d_in, const int* in_sizes, int n_in,
                              void* d_out, int out_size) {
    const float* x      = (const float*)d_in[0];   // (16, 512, 4096)
    const float* gumbel = (const float*)d_in[1];   // (16, 4096, 2, 320)
    const float* proj_w = (const float*)d_in[2];   // (640, 512)
    const float* proj_b = (const float*)d_in[3];   // (640,)
    const float* cv     = (const float*)d_in[4];   // (1, 640, 128)

    float* out    = (float*)d_out;
    float* logits = out;
    float* q      = out + LOGITS_ELEMS;

    split_w_kernel<<<(NCOLS * KDIM + 1023) / 1024, 1024>>>(proj_w);
    split_x_kernel<<<dim3(TSEQ / 32, KDIM / 32, BATCH), dim3(32, 8)>>>(x);

    cudaFuncSetAttribute(pq_gemm_kernel,
                         cudaFuncAttributeMaxDynamicSharedMemorySize, SMEM_BYTES);
    pq_gemm_kernel<<<dim3(NCOLS / N_TILE, MROWS / M_TILE), THREADS, SMEM_BYTES>>>(
        proj_b, logits);

    int blocks = (MROWS * NGROUPS * 32 + 255) / 256;
    pq_argmax_gather_kernel<<<blocks, 256>>>(logits, gumbel, cv, q);
}

// round 4
// speedup vs baseline: 2.2801x; 1.2745x over previous
#include <cuda_runtime.h>
#include <cuda_bf16.h>
#include <cstdint>

// ---------------- problem constants ----------------
#define BATCH    16
#define ZDIM     512
#define TSEQ     4096
#define NGROUPS  2
#define NENTRIES 320
#define VDIM     128
#define MROWS    (BATCH * TSEQ)          // 65536
#define NCOLS    (NGROUPS * NENTRIES)    // 640
#define KDIM     ZDIM                    // 512
#define LOGITS_ELEMS ((size_t)MROWS * NCOLS)

// ---------------- GEMM tiling ----------------
#define M_TILE   128
#define N_TILE   128
#define KC       32                      // k per chunk
#define NCHUNK   (KDIM / KC)             // 16
#define THREADS  256

// SMEM: A bf16 double buffer (k-major) + B 4-stage ring
#define ABF_SLOT   16384                 // Ahi 8K + Alo 8K (32 k-rows x 256B)
#define OFF_ABF    0                     // 2 slots = 32 KB
#define OFF_B      32768
#define BSTAGE     16384                 // Bhi 8K + Blo 8K
#define SMEM_BYTES (OFF_B + 4 * BSTAGE)  // 96 KB

// ---------------- device scratch (weight splits only) ----------------
__device__ __nv_bfloat16 g_whi[NCOLS * KDIM];
__device__ __nv_bfloat16 g_wlo[NCOLS * KDIM];

__device__ __forceinline__ uint32_t smem_u32(const void* p) {
    uint32_t a;
    asm("{ .reg .u64 t; cvta.to.shared.u64 t, %1; cvt.u32.u64 %0, t; }" : "=r"(a) : "l"(p));
    return a;
}

#define CP_ASYNC16(dst, src) \
    asm volatile("cp.async.cg.shared.global [%0], [%1], 16;" :: "r"(dst), "l"(src))
#define CP_COMMIT() asm volatile("cp.async.commit_group;")
#define CP_WAIT2()  asm volatile("cp.async.wait_group 2;")

__device__ __forceinline__ void ldm_x4(uint32_t addr, uint32_t& r0, uint32_t& r1,
                                       uint32_t& r2, uint32_t& r3) {
    asm volatile("ldmatrix.sync.aligned.m8n8.x4.shared.b16 {%0,%1,%2,%3}, [%4];"
                 : "=r"(r0), "=r"(r1), "=r"(r2), "=r"(r3) : "r"(addr));
}
__device__ __forceinline__ void ldm_x4t(uint32_t addr, uint32_t& r0, uint32_t& r1,
                                        uint32_t& r2, uint32_t& r3) {
    asm volatile("ldmatrix.sync.aligned.m8n8.x4.trans.shared.b16 {%0,%1,%2,%3}, [%4];"
                 : "=r"(r0), "=r"(r1), "=r"(r2), "=r"(r3) : "r"(addr));
}

__device__ __forceinline__ void mma_bf16(float& c0, float& c1, float& c2, float& c3,
                                         uint32_t a0, uint32_t a1, uint32_t a2, uint32_t a3,
                                         uint32_t b0, uint32_t b1) {
    asm volatile("mma.sync.aligned.m16n8k16.row.col.f32.bf16.bf16.f32 "
                 "{%0,%1,%2,%3}, {%4,%5,%6,%7}, {%8,%9}, {%0,%1,%2,%3};"
                 : "+f"(c0), "+f"(c1), "+f"(c2), "+f"(c3)
                 : "r"(a0), "r"(a1), "r"(a2), "r"(a3), "r"(b0), "r"(b1));
}

// B smem (64B rows): 16B-unit swizzle, conflict-free for cp.async + ldmatrix
__device__ __forceinline__ uint32_t sw_off_b(int row, int c16) {
    return (uint32_t)(row * 64 + ((c16 ^ ((row >> 1) & 3)) << 4));
}
// A smem (k-major, 256B rows of 128 m bf16): unit16 XORed with (k&7)
__device__ __forceinline__ uint32_t sw_off_a(int krow, int munit) {
    return (uint32_t)(krow * 256 + ((munit ^ (krow & 7)) << 4));
}

// ============================================================
// Pre-pass: split proj_w (640, 512) fp32 -> bf16 hi/lo
// ============================================================
__global__ __launch_bounds__(1024)
void split_w_kernel(const float* __restrict__ w) {
    int idx = blockIdx.x * blockDim.x + threadIdx.x;
    if (idx < NCOLS * KDIM) {
        float v = w[idx];
        __nv_bfloat16 hi = __float2bfloat16(v);
        g_whi[idx] = hi;
        g_wlo[idx] = __float2bfloat16(v - __bfloat162float(hi));
    }
}

// ============================================================
// GEMM: logits = x^T W^T + b via 3-product bf16 split,
// x read directly (fp32) + in-kernel hi/lo conversion.
// grid = (5, 512), 256 threads, warp grid 4m x 2n, warp tile 32x64.
// ============================================================
__global__ __launch_bounds__(THREADS, 2)
void pq_gemm_kernel(const float* __restrict__ x,      // (B, Z, T)
                    const float* __restrict__ bias,
                    float* __restrict__ logits)
{
    extern __shared__ char smem[];
    const uint32_t sbase = smem_u32(smem);
    const int tid  = threadIdx.x;
    const int wid  = tid >> 5;
    const int lane = tid & 31;
    const int m0   = blockIdx.y * M_TILE;
    const int n0   = blockIdx.x * N_TILE;
    const int b    = m0 >> 12;
    const int t0   = m0 & 4095;

    const int mwarp = wid >> 1;          // 0..3
    const int nwarp = wid & 1;           // 0..1

    float acc[2][8][4];
#pragma unroll
    for (int mi = 0; mi < 2; mi++)
#pragma unroll
        for (int nf = 0; nf < 8; nf++)
#pragma unroll
            for (int r = 0; r < 4; r++) acc[mi][nf][r] = 0.0f;

    // ---- A direct-load mapping: warp w owns k-rows w*4..w*4+3; lane owns 4 t ----
    const float* xrow0 = x + ((size_t)b * KDIM + (size_t)(wid * 4)) * TSEQ + t0 + lane * 4;
    float4 areg[4];

    // ---- B cp.async mapping (as round 3) ----
    const int lrow = tid >> 1;           // 0..127 (n row)
    const int lcb  = (tid & 1) * 2;

    auto issue_b = [&](int c) {
        const int kk = c * KC;
        const uint32_t st = sbase + OFF_B + (uint32_t)(c & 3) * BSTAGE;
#pragma unroll
        for (int u = 0; u < 2; u++) {
            int c16 = lcb + u;
            uint32_t so = sw_off_b(lrow, c16);
            const __nv_bfloat16* gh = g_whi + (size_t)(n0 + lrow) * KDIM + kk + c16 * 8;
            const __nv_bfloat16* gl = g_wlo + (size_t)(n0 + lrow) * KDIM + kk + c16 * 8;
            CP_ASYNC16(st + so, gh);
            CP_ASYNC16(st + 8192 + so, gl);
        }
        CP_COMMIT();
    };

    auto lda = [&](int c) {
#pragma unroll
        for (int i = 0; i < 4; i++)
            areg[i] = *(const float4*)(xrow0 + ((size_t)(c * KC) + i) * TSEQ);
    };

    // prologue
    lda(0);
    issue_b(0); issue_b(1); issue_b(2);

    for (int c = 0; c < NCHUNK; ++c) {
        // ---- convert A regs -> bf16 hi/lo smem (k-major, swizzled) ----
        {
            char* abuf = smem + OFF_ABF + (c & 1) * ABF_SLOT;
#pragma unroll
            for (int i = 0; i < 4; i++) {
                float4 v = areg[i];
                int k = wid * 4 + i;
                uint32_t off = (uint32_t)(k * 256) +
                               ((((uint32_t)(lane >> 1)) ^ (uint32_t)(k & 7)) << 4) +
                               (uint32_t)((lane & 1) * 8);
                __nv_bfloat16 h0 = __float2bfloat16(v.x);
                __nv_bfloat16 h1 = __float2bfloat16(v.y);
                __nv_bfloat16 h2 = __float2bfloat16(v.z);
                __nv_bfloat16 h3 = __float2bfloat16(v.w);
                __nv_bfloat162 hp0 = __halves2bfloat162(h0, h1);
                __nv_bfloat162 hp1 = __halves2bfloat162(h2, h3);
                *(uint2*)(abuf + off) = *(uint2*)&hp0;  // hp0,hp1 adjacent
                ((uint2*)(abuf + off))[0] = make_uint2(*(uint32_t*)&hp0, *(uint32_t*)&hp1);
                __nv_bfloat162 lp0 = __halves2bfloat162(
                    __float2bfloat16(v.x - __bfloat162float(h0)),
                    __float2bfloat16(v.y - __bfloat162float(h1)));
                __nv_bfloat162 lp1 = __halves2bfloat162(
                    __float2bfloat16(v.z - __bfloat162float(h2)),
                    __float2bfloat16(v.w - __bfloat162float(h3)));
                ((uint2*)(abuf + 8192 + off))[0] = make_uint2(*(uint32_t*)&lp0, *(uint32_t*)&lp1);
            }
        }
        if (c + 1 < NCHUNK) lda(c + 1);   // overlap LDG with MMA below

        CP_WAIT2();
        __syncthreads();
        if (c + 3 < NCHUNK) issue_b(c + 3);
        else CP_COMMIT();

        const uint32_t abase = sbase + OFF_ABF + (uint32_t)(c & 1) * ABF_SLOT;
        const uint32_t bbase = sbase + OFF_B + (uint32_t)(c & 3) * BSTAGE;

        const int grp = lane >> 3;
        const int kq  = lane & 7;

#pragma unroll
        for (int ks = 0; ks < 2; ks++) {
            const int arow = ks * 16 + ((grp >> 1) << 3) + kq;   // k-row in chunk
            // A hi fragments (ldmatrix.trans from k-major)
            uint32_t ah[2][4];
#pragma unroll
            for (int mi = 0; mi < 2; mi++) {
                int munit = ((mwarp * 32 + mi * 16) >> 3) + (grp & 1);
                ldm_x4t(abase + sw_off_a(arow, munit), ah[mi][0], ah[mi][1], ah[mi][2], ah[mi][3]);
            }
            // B hi fragments
            const int brow = nwarp * 64 + (lane & 7) + ((lane >> 4) << 3);
            const int bc16 = ks * 2 + ((lane >> 3) & 1);
            uint32_t bh[4][4];
#pragma unroll
            for (int j = 0; j < 4; j++)
                ldm_x4(bbase + sw_off_b(brow + j * 16, bc16), bh[j][0], bh[j][1], bh[j][2], bh[j][3]);

            // product 1: Ahi x Bhi
#pragma unroll
            for (int mi = 0; mi < 2; mi++)
#pragma unroll
                for (int nf = 0; nf < 8; nf++) {
                    int j = nf >> 1, h = (nf & 1) * 2;
                    mma_bf16(acc[mi][nf][0], acc[mi][nf][1], acc[mi][nf][2], acc[mi][nf][3],
                             ah[mi][0], ah[mi][1], ah[mi][2], ah[mi][3], bh[j][h], bh[j][h + 1]);
                }

            // product 2: Ahi x Blo
            uint32_t bl[4][4];
#pragma unroll
            for (int j = 0; j < 4; j++)
                ldm_x4(bbase + 8192 + sw_off_b(brow + j * 16, bc16), bl[j][0], bl[j][1], bl[j][2], bl[j][3]);
#pragma unroll
            for (int mi = 0; mi < 2; mi++)
#pragma unroll
                for (int nf = 0; nf < 8; nf++) {
                    int j = nf >> 1, h = (nf & 1) * 2;
                    mma_bf16(acc[mi][nf][0], acc[mi][nf][1], acc[mi][nf][2], acc[mi][nf][3],
                             ah[mi][0], ah[mi][1], ah[mi][2], ah[mi][3], bl[j][h], bl[j][h + 1]);
                }

            // product 3: Alo x Bhi
            uint32_t al[2][4];
#pragma unroll
            for (int mi = 0; mi < 2; mi++) {
                int munit = ((mwarp * 32 + mi * 16) >> 3) + (grp & 1);
                ldm_x4t(abase + 8192 + sw_off_a(arow, munit), al[mi][0], al[mi][1], al[mi][2], al[mi][3]);
            }
#pragma unroll
            for (int mi = 0; mi < 2; mi++)
#pragma unroll
                for (int nf = 0; nf < 8; nf++) {
                    int j = nf >> 1, h = (nf & 1) * 2;
                    mma_bf16(acc[mi][nf][0], acc[mi][nf][1], acc[mi][nf][2], acc[mi][nf][3],
                             al[mi][0], al[mi][1], al[mi][2], al[mi][3], bh[j][h], bh[j][h + 1]);
                }
        }
    }

    // ---- epilogue: bias add + store ----
#pragma unroll
    for (int nf = 0; nf < 8; nf++) {
        int col = n0 + nwarp * 64 + nf * 8 + (lane & 3) * 2;
        float b0 = __ldg(bias + col);
        float b1 = __ldg(bias + col + 1);
#pragma unroll
        for (int mi = 0; mi < 2; mi++) {
            int row = m0 + mwarp * 32 + mi * 16 + (lane >> 2);
            float2 v0 = make_float2(acc[mi][nf][0] + b0, acc[mi][nf][1] + b1);
            float2 v1 = make_float2(acc[mi][nf][2] + b0, acc[mi][nf][3] + b1);
            *(float2*)(logits + (size_t)row * NCOLS + col)       = v0;
            *(float2*)(logits + (size_t)(row + 8) * NCOLS + col) = v1;
        }
    }
}

// ============================================================
// Argmax + gather (at DRAM roofline; unchanged)
// ============================================================
__global__ __launch_bounds__(256)
void pq_argmax_gather_kernel(const float* __restrict__ logits,
                             const float* __restrict__ gumbel,
                             const float* __restrict__ cv,
                             float* __restrict__ q)
{
    const int warp = (blockIdx.x * blockDim.x + threadIdx.x) >> 5;
    const int lane = threadIdx.x & 31;
    if (warp >= MROWS * NGROUPS) return;

    const int bt = warp >> 1;
    const int g  = warp & 1;

    const float* lp = logits + (size_t)bt * NCOLS + g * NENTRIES;
    const float* gp = gumbel + (size_t)bt * NCOLS + g * NENTRIES;

    float best = -3.4e38f;
    int   bidx = 0;
#pragma unroll
    for (int j = 0; j < NENTRIES / 32; j++) {
        int e = lane + j * 32;
        float v = lp[e] + gp[e];
        if (v > best) { best = v; bidx = e; }
    }
#pragma unroll
    for (int off = 16; off > 0; off >>= 1) {
        float ov = __shfl_down_sync(0xffffffffu, best, off);
        int   oi = __shfl_down_sync(0xffffffffu, bidx, off);
        if (ov > best || (ov == best && oi < bidx)) { best = ov; bidx = oi; }
    }
    bidx = __shfl_sync(0xffffffffu, bidx, 0);

    const float4* src = (const float4*)(cv + ((size_t)g * NENTRIES + bidx) * VDIM);
    float4*       dst = (float4*)(q + (size_t)bt * (NGROUPS * VDIM) + g * VDIM);
    dst[lane] = src[lane];
}

// ============================================================
extern "C" void kernel_launch(void* const* d_in, const int* in_sizes, int n_in,
                              void* d_out, int out_size) {
    const float* x      = (const float*)d_in[0];   // (16, 512, 4096)
    const float* gumbel = (const float*)d_in[1];   // (16, 4096, 2, 320)
    const float* proj_w = (const float*)d_in[2];   // (640, 512)
    const float* proj_b = (const float*)d_in[3];   // (640,)
    const float* cv     = (const float*)d_in[4];   // (1, 640, 128)

    float* out    = (float*)d_out;
    float* logits = out;
    float* q      = out + LOGITS_ELEMS;

    split_w_kernel<<<(NCOLS * KDIM + 1023) / 1024, 1024>>>(proj_w);

    cudaFuncSetAttribute(pq_gemm_kernel,
                         cudaFuncAttributeMaxDynamicSharedMemorySize, SMEM_BYTES);
    pq_gemm_kernel<<<dim3(NCOLS / N_TILE, MROWS / M_TILE), THREADS, SMEM_BYTES>>>(
        x, proj_b, logits);

    int blocks = (MROWS * NGROUPS * 32 + 255) / 256;
    pq_argmax_gather_kernel<<<blocks, 256>>>(logits, gumbel, cv, q);
}

// round 5
// speedup vs baseline: 2.4151x; 1.0592x over previous
#include <cuda_runtime.h>
#include <cuda_bf16.h>
#include <cstdint>

// ---------------- problem constants ----------------
#define BATCH    16
#define ZDIM     512
#define TSEQ     4096
#define NGROUPS  2
#define NENTRIES 320
#define VDIM     128
#define MROWS    (BATCH * TSEQ)          // 65536
#define NCOLS    (NGROUPS * NENTRIES)    // 640
#define KDIM     ZDIM                    // 512
#define LOGITS_ELEMS ((size_t)MROWS * NCOLS)

// ---------------- GEMM tiling ----------------
#define M_TILE   128
#define N_TILE   128
#define KC       32
#define NCHUNK   (KDIM / KC)             // 16
#define THREADS  256
#define NHALVES  10                      // 640 / 64

// SMEM: A bf16 double buffer (k-major) + B 4-stage ring
#define ABF_SLOT   16384
#define OFF_ABF    0
#define OFF_B      32768
#define BSTAGE     16384
#define SMEM_BYTES (OFF_B + 4 * BSTAGE)  // 96 KB

// ---------------- device scratch ----------------
__device__ __nv_bfloat16 g_whi[NCOLS * KDIM];
__device__ __nv_bfloat16 g_wlo[NCOLS * KDIM];
__device__ float2 g_part[(size_t)NHALVES * MROWS];   // (val, idx-bits) per 64-col half

__device__ __forceinline__ uint32_t smem_u32(const void* p) {
    uint32_t a;
    asm("{ .reg .u64 t; cvta.to.shared.u64 t, %1; cvt.u32.u64 %0, t; }" : "=r"(a) : "l"(p));
    return a;
}

#define CP_ASYNC16(dst, src) \
    asm volatile("cp.async.cg.shared.global [%0], [%1], 16;" :: "r"(dst), "l"(src))
#define CP_COMMIT() asm volatile("cp.async.commit_group;")
#define CP_WAIT2()  asm volatile("cp.async.wait_group 2;")

__device__ __forceinline__ void ldm_x4(uint32_t addr, uint32_t& r0, uint32_t& r1,
                                       uint32_t& r2, uint32_t& r3) {
    asm volatile("ldmatrix.sync.aligned.m8n8.x4.shared.b16 {%0,%1,%2,%3}, [%4];"
                 : "=r"(r0), "=r"(r1), "=r"(r2), "=r"(r3) : "r"(addr));
}
__device__ __forceinline__ void ldm_x4t(uint32_t addr, uint32_t& r0, uint32_t& r1,
                                        uint32_t& r2, uint32_t& r3) {
    asm volatile("ldmatrix.sync.aligned.m8n8.x4.trans.shared.b16 {%0,%1,%2,%3}, [%4];"
                 : "=r"(r0), "=r"(r1), "=r"(r2), "=r"(r3) : "r"(addr));
}

__device__ __forceinline__ void mma_bf16(float& c0, float& c1, float& c2, float& c3,
                                         uint32_t a0, uint32_t a1, uint32_t a2, uint32_t a3,
                                         uint32_t b0, uint32_t b1) {
    asm volatile("mma.sync.aligned.m16n8k16.row.col.f32.bf16.bf16.f32 "
                 "{%0,%1,%2,%3}, {%4,%5,%6,%7}, {%8,%9}, {%0,%1,%2,%3};"
                 : "+f"(c0), "+f"(c1), "+f"(c2), "+f"(c3)
                 : "r"(a0), "r"(a1), "r"(a2), "r"(a3), "r"(b0), "r"(b1));
}

__device__ __forceinline__ uint32_t sw_off_b(int row, int c16) {
    return (uint32_t)(row * 64 + ((c16 ^ ((row >> 1) & 3)) << 4));
}
__device__ __forceinline__ uint32_t sw_off_a(int krow, int munit) {
    return (uint32_t)(krow * 256 + ((munit ^ (krow & 7)) << 4));
}

// ============================================================
// Pre-pass: split proj_w fp32 -> bf16 hi/lo
// ============================================================
__global__ __launch_bounds__(1024)
void split_w_kernel(const float* __restrict__ w) {
    int idx = blockIdx.x * blockDim.x + threadIdx.x;
    if (idx < NCOLS * KDIM) {
        float v = w[idx];
        __nv_bfloat16 hi = __float2bfloat16(v);
        g_whi[idx] = hi;
        g_wlo[idx] = __float2bfloat16(v - __bfloat162float(hi));
    }
}

// ============================================================
// GEMM + fused logits write + per-half perturbed partial argmax
// ============================================================
__global__ __launch_bounds__(THREADS, 2)
void pq_gemm_kernel(const float* __restrict__ x,      // (B, Z, T)
                    const float* __restrict__ bias,
                    const float* __restrict__ gumbel,  // (BT, 640)
                    float* __restrict__ logits)
{
    extern __shared__ char smem[];
    const uint32_t sbase = smem_u32(smem);
    const int tid  = threadIdx.x;
    const int wid  = tid >> 5;
    const int lane = tid & 31;
    const int m0   = blockIdx.y * M_TILE;
    const int n0   = blockIdx.x * N_TILE;
    const int b    = m0 >> 12;
    const int t0   = m0 & 4095;

    const int mwarp = wid >> 1;
    const int nwarp = wid & 1;

    float acc[2][8][4];
#pragma unroll
    for (int mi = 0; mi < 2; mi++)
#pragma unroll
        for (int nf = 0; nf < 8; nf++)
#pragma unroll
            for (int r = 0; r < 4; r++) acc[mi][nf][r] = 0.0f;

    const float* xrow0 = x + ((size_t)b * KDIM + (size_t)(wid * 4)) * TSEQ + t0 + lane * 4;
    float4 areg[4];

    const int lrow = tid >> 1;
    const int lcb  = (tid & 1) * 2;

    auto issue_b = [&](int c) {
        const int kk = c * KC;
        const uint32_t st = sbase + OFF_B + (uint32_t)(c & 3) * BSTAGE;
#pragma unroll
        for (int u = 0; u < 2; u++) {
            int c16 = lcb + u;
            uint32_t so = sw_off_b(lrow, c16);
            const __nv_bfloat16* gh = g_whi + (size_t)(n0 + lrow) * KDIM + kk + c16 * 8;
            const __nv_bfloat16* gl = g_wlo + (size_t)(n0 + lrow) * KDIM + kk + c16 * 8;
            CP_ASYNC16(st + so, gh);
            CP_ASYNC16(st + 8192 + so, gl);
        }
        CP_COMMIT();
    };

    auto lda = [&](int c) {
#pragma unroll
        for (int i = 0; i < 4; i++)
            areg[i] = *(const float4*)(xrow0 + ((size_t)(c * KC) + i) * TSEQ);
    };

    lda(0);
    issue_b(0); issue_b(1); issue_b(2);

    for (int c = 0; c < NCHUNK; ++c) {
        {
            char* abuf = smem + OFF_ABF + (c & 1) * ABF_SLOT;
#pragma unroll
            for (int i = 0; i < 4; i++) {
                float4 v = areg[i];
                int k = wid * 4 + i;
                uint32_t off = (uint32_t)(k * 256) +
                               ((((uint32_t)(lane >> 1)) ^ (uint32_t)(k & 7)) << 4) +
                               (uint32_t)((lane & 1) * 8);
                __nv_bfloat16 h0 = __float2bfloat16(v.x);
                __nv_bfloat16 h1 = __float2bfloat16(v.y);
                __nv_bfloat16 h2 = __float2bfloat16(v.z);
                __nv_bfloat16 h3 = __float2bfloat16(v.w);
                __nv_bfloat162 hp0 = __halves2bfloat162(h0, h1);
                __nv_bfloat162 hp1 = __halves2bfloat162(h2, h3);
                ((uint2*)(abuf + off))[0] = make_uint2(*(uint32_t*)&hp0, *(uint32_t*)&hp1);
                __nv_bfloat162 lp0 = __halves2bfloat162(
                    __float2bfloat16(v.x - __bfloat162float(h0)),
                    __float2bfloat16(v.y - __bfloat162float(h1)));
                __nv_bfloat162 lp1 = __halves2bfloat162(
                    __float2bfloat16(v.z - __bfloat162float(h2)),
                    __float2bfloat16(v.w - __bfloat162float(h3)));
                ((uint2*)(abuf + 8192 + off))[0] = make_uint2(*(uint32_t*)&lp0, *(uint32_t*)&lp1);
            }
        }
        if (c + 1 < NCHUNK) lda(c + 1);

        CP_WAIT2();
        __syncthreads();
        if (c + 3 < NCHUNK) issue_b(c + 3);
        else CP_COMMIT();

        const uint32_t abase = sbase + OFF_ABF + (uint32_t)(c & 1) * ABF_SLOT;
        const uint32_t bbase = sbase + OFF_B + (uint32_t)(c & 3) * BSTAGE;

        const int grp = lane >> 3;
        const int kq  = lane & 7;

#pragma unroll
        for (int ks = 0; ks < 2; ks++) {
            const int arow = ks * 16 + ((grp >> 1) << 3) + kq;
            uint32_t ah[2][4];
#pragma unroll
            for (int mi = 0; mi < 2; mi++) {
                int munit = ((mwarp * 32 + mi * 16) >> 3) + (grp & 1);
                ldm_x4t(abase + sw_off_a(arow, munit), ah[mi][0], ah[mi][1], ah[mi][2], ah[mi][3]);
            }
            const int brow = nwarp * 64 + (lane & 7) + ((lane >> 4) << 3);
            const int bc16 = ks * 2 + ((lane >> 3) & 1);
            uint32_t bh[4][4];
#pragma unroll
            for (int j = 0; j < 4; j++)
                ldm_x4(bbase + sw_off_b(brow + j * 16, bc16), bh[j][0], bh[j][1], bh[j][2], bh[j][3]);

#pragma unroll
            for (int mi = 0; mi < 2; mi++)
#pragma unroll
                for (int nf = 0; nf < 8; nf++) {
                    int j = nf >> 1, h = (nf & 1) * 2;
                    mma_bf16(acc[mi][nf][0], acc[mi][nf][1], acc[mi][nf][2], acc[mi][nf][3],
                             ah[mi][0], ah[mi][1], ah[mi][2], ah[mi][3], bh[j][h], bh[j][h + 1]);
                }

            uint32_t bl[4][4];
#pragma unroll
            for (int j = 0; j < 4; j++)
                ldm_x4(bbase + 8192 + sw_off_b(brow + j * 16, bc16), bl[j][0], bl[j][1], bl[j][2], bl[j][3]);
#pragma unroll
            for (int mi = 0; mi < 2; mi++)
#pragma unroll
                for (int nf = 0; nf < 8; nf++) {
                    int j = nf >> 1, h = (nf & 1) * 2;
                    mma_bf16(acc[mi][nf][0], acc[mi][nf][1], acc[mi][nf][2], acc[mi][nf][3],
                             ah[mi][0], ah[mi][1], ah[mi][2], ah[mi][3], bl[j][h], bl[j][h + 1]);
                }

            uint32_t al[2][4];
#pragma unroll
            for (int mi = 0; mi < 2; mi++) {
                int munit = ((mwarp * 32 + mi * 16) >> 3) + (grp & 1);
                ldm_x4t(abase + 8192 + sw_off_a(arow, munit), al[mi][0], al[mi][1], al[mi][2], al[mi][3]);
            }
#pragma unroll
            for (int mi = 0; mi < 2; mi++)
#pragma unroll
                for (int nf = 0; nf < 8; nf++) {
                    int j = nf >> 1, h = (nf & 1) * 2;
                    mma_bf16(acc[mi][nf][0], acc[mi][nf][1], acc[mi][nf][2], acc[mi][nf][3],
                             al[mi][0], al[mi][1], al[mi][2], al[mi][3], bh[j][h], bh[j][h + 1]);
                }
        }
    }

    // ---- fused epilogue: bias + logits store + perturbed partial argmax ----
    float bestv[4];
    int   besti[4];
#pragma unroll
    for (int rp = 0; rp < 4; rp++) { bestv[rp] = -3.4e38f; besti[rp] = 0; }

#pragma unroll
    for (int nf = 0; nf < 8; nf++) {
        int col = n0 + nwarp * 64 + nf * 8 + (lane & 3) * 2;
        float b0 = __ldg(bias + col);
        float b1 = __ldg(bias + col + 1);
#pragma unroll
        for (int mi = 0; mi < 2; mi++) {
            int row = m0 + mwarp * 32 + mi * 16 + (lane >> 2);
            float v00 = acc[mi][nf][0] + b0, v01 = acc[mi][nf][1] + b1;
            float v10 = acc[mi][nf][2] + b0, v11 = acc[mi][nf][3] + b1;
            *(float2*)(logits + (size_t)row * NCOLS + col)       = make_float2(v00, v01);
            *(float2*)(logits + (size_t)(row + 8) * NCOLS + col) = make_float2(v10, v11);
            float2 g0 = *(const float2*)(gumbel + (size_t)row * NCOLS + col);
            float2 g1 = *(const float2*)(gumbel + (size_t)(row + 8) * NCOLS + col);
            float p;
            int rp0 = mi * 2, rp1 = mi * 2 + 1;
            p = v00 + g0.x; if (p > bestv[rp0]) { bestv[rp0] = p; besti[rp0] = col; }
            p = v01 + g0.y; if (p > bestv[rp0]) { bestv[rp0] = p; besti[rp0] = col + 1; }
            p = v10 + g1.x; if (p > bestv[rp1]) { bestv[rp1] = p; besti[rp1] = col; }
            p = v11 + g1.y; if (p > bestv[rp1]) { bestv[rp1] = p; besti[rp1] = col + 1; }
        }
    }

    // reduce across the 4 lanes sharing each row (lane bits 0..1)
#pragma unroll
    for (int rp = 0; rp < 4; rp++) {
#pragma unroll
        for (int off = 1; off <= 2; off <<= 1) {
            float ov = __shfl_xor_sync(0xffffffffu, bestv[rp], off);
            int   oi = __shfl_xor_sync(0xffffffffu, besti[rp], off);
            if (ov > bestv[rp] || (ov == bestv[rp] && oi < besti[rp])) {
                bestv[rp] = ov; besti[rp] = oi;
            }
        }
    }
    if ((lane & 3) == 0) {
        const int h = blockIdx.x * 2 + nwarp;            // 64-col half index 0..9
#pragma unroll
        for (int rp = 0; rp < 4; rp++) {
            int row = m0 + mwarp * 32 + (rp >> 1) * 16 + (rp & 1) * 8 + (lane >> 2);
            g_part[(size_t)h * MROWS + row] = make_float2(bestv[rp], __int_as_float(besti[rp]));
        }
    }
}

// ============================================================
// Combine: pick winner among 5 halves per group, gather codevector
// ============================================================
__global__ __launch_bounds__(256)
void pq_combine_kernel(const float* __restrict__ cv,   // (640, 128)
                       float* __restrict__ q)          // (BT, 256)
{
    const int warp = (blockIdx.x * blockDim.x + threadIdx.x) >> 5;
    const int lane = threadIdx.x & 31;
    if (warp >= MROWS * NGROUPS) return;

    const int bt = warp >> 1;
    const int g  = warp & 1;

    float best = -3.4e38f;
    int   bcol = 0;
#pragma unroll
    for (int j = 0; j < 5; j++) {
        float2 p = g_part[(size_t)(g * 5 + j) * MROWS + bt];
        if (p.x > best) { best = p.x; bcol = __float_as_int(p.y); }
    }

    const float4* src = (const float4*)(cv + (size_t)bcol * VDIM);
    float4*       dst = (float4*)(q + (size_t)bt * (NGROUPS * VDIM) + g * VDIM);
    dst[lane] = src[lane];
}

// ============================================================
extern "C" void kernel_launch(void* const* d_in, const int* in_sizes, int n_in,
                              void* d_out, int out_size) {
    const float* x      = (const float*)d_in[0];
    const float* gumbel = (const float*)d_in[1];
    const float* proj_w = (const float*)d_in[2];
    const float* proj_b = (const float*)d_in[3];
    const float* cv     = (const float*)d_in[4];

    float* out    = (float*)d_out;
    float* logits = out;
    float* q      = out + LOGITS_ELEMS;

    split_w_kernel<<<(NCOLS * KDIM + 1023) / 1024, 1024>>>(proj_w);

    cudaFuncSetAttribute(pq_gemm_kernel,
                         cudaFuncAttributeMaxDynamicSharedMemorySize, SMEM_BYTES);
    pq_gemm_kernel<<<dim3(NCOLS / N_TILE, MROWS / M_TILE), THREADS, SMEM_BYTES>>>(
        x, proj_b, gumbel, logits);

    int blocks = (MROWS * NGROUPS * 32 + 255) / 256;
    pq_combine_kernel<<<blocks, 256>>>(cv, q);
}